// round 1
// baseline (speedup 1.0000x reference)
#include <cuda_runtime.h>
#include <cuda_fp16.h>
#include <cstdint>

// Problem constants
#define NB 8
#define CI 512
#define CO 512
#define HH 64
#define WW 64
// 1/sqrt(512), 1/sqrt(512*9), (1/sqrt(4608))^2
#define DENSE_SCALE 0.04419417382415922f
#define CONV_SCALE  0.014731391274719742f
#define CONV_SCALE2 (1.0f/4608.0f)

// ---------------- device scratch (allowed: __device__ globals) ----------------
__device__ float  g_style[NB*CI];                      // [b][i]
__device__ float  g_w2[CO*CI];                         // sum_k w^2  [o][i]
__device__ float  g_d[NB*CO];                          // demod      [b][o]
__device__ __half g_wh[(size_t)9*CO*CI];               // fp16 w*scale, [tap][o][i]
__device__ __half g_xs[(size_t)NB*CI*HH*WW];           // fp16 x*style, [b][i][h][w]

// ---------------- prep kernels ----------------
__global__ void k_style(const float* __restrict__ dl, const float* __restrict__ dw,
                        const float* __restrict__ db) {
    int idx = blockIdx.x * 256 + threadIdx.x;       // b*512 + i
    int b = idx >> 9, i = idx & 511;
    const float* dlr = dl + b * 512;
    const float* dwr = dw + i * 512;
    float acc = 0.f;
#pragma unroll 8
    for (int d = 0; d < 512; d++) acc = fmaf(dlr[d], dwr[d], acc);
    g_style[idx] = acc * DENSE_SCALE + db[i];
}

__global__ void k_wprep(const float* __restrict__ w) {
    int idx = blockIdx.x * 256 + threadIdx.x;       // o*512 + i
    const float* wp = w + (size_t)idx * 9;
    float s2 = 0.f;
#pragma unroll
    for (int t = 0; t < 9; t++) {
        float v = wp[t];
        s2 = fmaf(v, v, s2);
        g_wh[(size_t)t * (CO * CI) + idx] = __float2half_rn(v * CONV_SCALE);
    }
    g_w2[idx] = s2;
}

__global__ void k_demod() {
    int idx = blockIdx.x * 256 + threadIdx.x;       // b*512 + o
    int b = idx >> 9, o = idx & 511;
    const float* w2r = g_w2 + o * 512;
    const float* sr  = g_style + b * 512;
    float acc = 0.f;
#pragma unroll 8
    for (int i = 0; i < 512; i++) { float s = sr[i]; acc = fmaf(w2r[i], s * s, acc); }
    g_d[idx] = rsqrtf(acc * CONV_SCALE2 + 1e-8f);
}

__global__ void k_xs(const float* __restrict__ x) {
    size_t idx  = (size_t)blockIdx.x * 256 + threadIdx.x;
    size_t base = idx * 4;                          // 4 consecutive pixels (same b,i)
    int bi = (int)(base >> 12);                     // b*512 + i  (HW = 4096)
    float s = g_style[bi];
    float4 v = *(const float4*)(x + base);
    __half2* o = (__half2*)(g_xs + base);
    o[0] = __floats2half2_rn(v.x * s, v.y * s);
    o[1] = __floats2half2_rn(v.z * s, v.w * s);
}

// ---------------- main conv (implicit GEMM, mma.sync fp16) ----------------
__device__ __forceinline__ uint32_t s2u(const void* p) {
    return (uint32_t)__cvta_generic_to_shared(p);
}
__device__ __forceinline__ void ldsm4(uint32_t& r0, uint32_t& r1, uint32_t& r2,
                                      uint32_t& r3, uint32_t a) {
    asm volatile("ldmatrix.sync.aligned.m8n8.x4.shared.b16 {%0,%1,%2,%3}, [%4];"
                 : "=r"(r0), "=r"(r1), "=r"(r2), "=r"(r3) : "r"(a));
}
__device__ __forceinline__ void mma16816(float* c, uint32_t a0, uint32_t a1, uint32_t a2,
                                         uint32_t a3, uint32_t b0, uint32_t b1) {
    asm volatile("mma.sync.aligned.m16n8k16.row.col.f32.f16.f16.f32 "
                 "{%0,%1,%2,%3}, {%4,%5,%6,%7}, {%8,%9}, {%0,%1,%2,%3};"
                 : "+f"(c[0]), "+f"(c[1]), "+f"(c[2]), "+f"(c[3])
                 : "r"(a0), "r"(a1), "r"(a2), "r"(a3), "r"(b0), "r"(b1));
}

// smem layout: xT [6 rows][66 cols][40 ci-pad] halves; w [9 taps][64 o][40 ci-pad]
#define XT_S   40
#define SMEM_X (6 * 66 * XT_S)
#define SMEM_W (9 * 64 * XT_S)
#define SMEM_BYTES ((SMEM_X + SMEM_W) * 2)

// Block: 64 o  x  256 px (4 rows x 64 cols) for one (b, h0). 256 thr, 8 warps (4m x 2n).
__global__ __launch_bounds__(256, 2) void k_conv(float* __restrict__ out) {
    extern __shared__ __half sh[];
    __half* xsm = sh;            // [(r*66+cl)*40 + ci]
    __half* wsm = sh + SMEM_X;   // [(tap*64+oo)*40 + ci]

    int tid = threadIdx.x;
    int b  = blockIdx.z;
    int ob = blockIdx.x * 64;
    int h0 = blockIdx.y * 4;
    int lane = tid & 31, warp = tid >> 5;
    int wm = warp & 3;           // o-subtile (16 rows)
    int wn = warp >> 2;          // pixel half (128 px)

    float acc[16][4];
#pragma unroll
    for (int i = 0; i < 16; i++)
#pragma unroll
        for (int j = 0; j < 4; j++) acc[i][j] = 0.f;

    const __half* xg = g_xs + (size_t)b * CI * HH * WW;
    int arow = wm * 16 + (lane & 15);
    int acol = (lane >> 4) << 3;

    for (int ic = 0; ic < CI; ic += 32) {
        // ---- load x tile: 6 input rows x 66 cols (halo) x 32 ci, transposed ----
        for (int idx = tid; idx < 6 * 66 * 32; idx += 256) {
            int cl = idx % 66;            // fastest: coalesced gmem along w
            int t  = idx / 66;
            int ci = t & 31;
            int r  = t >> 5;
            int ri = h0 - 1 + r;
            int wi = cl - 1;
            __half v;
            if ((unsigned)ri < 64u && (unsigned)wi < 64u)
                v = xg[(size_t)(ic + ci) * 4096 + ri * 64 + wi];
            else
                v = __float2half(0.f);
            xsm[(r * 66 + cl) * XT_S + ci] = v;
        }
        // ---- load w tile: 9 taps x 64 o x 32 ci ----
        for (int idx = tid; idx < 9 * 64 * 32; idx += 256) {
            int ci  = idx & 31;
            int oo  = (idx >> 5) & 63;
            int tap = idx >> 11;
            wsm[(tap * 64 + oo) * XT_S + ci] =
                g_wh[(size_t)tap * (CO * CI) + (ob + oo) * 512 + ic + ci];
        }
        __syncthreads();

#pragma unroll
        for (int dy = 0; dy < 3; dy++) {
#pragma unroll
            for (int dx = 0; dx < 3; dx++) {
                int tap = dy * 3 + dx;
#pragma unroll
                for (int k0 = 0; k0 < 32; k0 += 16) {
                    uint32_t a0, a1, a2, a3;
                    ldsm4(a0, a1, a2, a3,
                          s2u(&wsm[(tap * 64 + arow) * XT_S + k0 + acol]));
#pragma unroll
                    for (int g = 0; g < 4; g++) {
                        int rl = wn * 2 + (g >> 1) + dy;          // input row in tile
                        int cl = ((g & 1) << 5) + dx + lane;      // halo col (+dx shift)
                        uint32_t ba = s2u(&xsm[(rl * 66 + cl) * XT_S + k0]);
                        uint32_t p0, p1, p2, p3, q0, q1, q2, q3;
                        ldsm4(p0, p1, p2, p3, ba);        // k0..k0+7
                        ldsm4(q0, q1, q2, q3, ba + 16);   // k0+8..k0+15
                        mma16816(acc[g * 4 + 0], a0, a1, a2, a3, p0, q0);
                        mma16816(acc[g * 4 + 1], a0, a1, a2, a3, p1, q1);
                        mma16816(acc[g * 4 + 2], a0, a1, a2, a3, p2, q2);
                        mma16816(acc[g * 4 + 3], a0, a1, a2, a3, p3, q3);
                    }
                }
            }
        }
        __syncthreads();
    }

    // ---- epilogue: scale by d[b,o], store fp32 ----
    int m1 = ob + wm * 16 + (lane >> 2);
    float d1 = g_d[b * 512 + m1];
    float d2 = g_d[b * 512 + m1 + 8];
#pragma unroll
    for (int g = 0; g < 4; g++) {
#pragma unroll
        for (int j = 0; j < 4; j++) {
            int nsub = wn * 128 + g * 32 + j * 8;
            int h    = h0 + (nsub >> 6);
            int col  = (nsub & 63) + ((lane & 3) << 1);
            float* op = out + (((size_t)b * 512 + m1) * 64 + h) * 64 + col;
            float2 v0; v0.x = acc[g * 4 + j][0] * d1; v0.y = acc[g * 4 + j][1] * d1;
            float2 v1; v1.x = acc[g * 4 + j][2] * d2; v1.y = acc[g * 4 + j][3] * d2;
            *(float2*)op = v0;
            *(float2*)(op + 8 * 64 * 64) = v1;   // rows m+8
        }
    }
}

// ---------------- launcher ----------------
extern "C" void kernel_launch(void* const* d_in, const int* in_sizes, int n_in,
                              void* d_out, int out_size) {
    const float* x  = (const float*)d_in[0];
    const float* dl = (const float*)d_in[1];
    const float* w  = (const float*)d_in[2];
    const float* dw = (const float*)d_in[3];
    const float* db = (const float*)d_in[4];
    float* out = (float*)d_out;

    k_style<<<16, 256>>>(dl, dw, db);              // [8,512]
    k_wprep<<<1024, 256>>>(w);                     // wh + w2
    k_demod<<<16, 256>>>();                        // d[b,o]
    k_xs<<<16384, 256>>>(x);                       // xs fp16
    cudaFuncSetAttribute(k_conv, cudaFuncAttributeMaxDynamicSharedMemorySize, SMEM_BYTES);
    k_conv<<<dim3(8, 16, 8), 256, SMEM_BYTES>>>(out);
}

// round 6
// speedup vs baseline: 2.1146x; 2.1146x over previous
#include <cuda_runtime.h>
#include <cuda_fp16.h>
#include <cstdint>

// Problem constants
#define NB 8
#define CI 512
#define CO 512
#define HH 64
#define WW 64
#define DENSE_SCALE 0.04419417382415922f
#define CONV_SCALE  0.014731391274719742f
#define CONV_SCALE2 (1.0f/4608.0f)

// ---------------- device scratch ----------------
__device__ float  g_style[NB*CI];
__device__ float  g_w2[CO*CI];
__device__ float  g_d[NB*CO];
__device__ __align__(1024) __half g_wh[(size_t)9*CO*CI];          // [tap][o][ci]
__device__ __align__(1024) __half g_xs2[(size_t)NB*HH*WW*CI];     // NHWC fp16

// ---------------- prep kernels ----------------
__global__ void k_style(const float* __restrict__ dl, const float* __restrict__ dw,
                        const float* __restrict__ db) {
    int idx = blockIdx.x * 256 + threadIdx.x;
    int b = idx >> 9, i = idx & 511;
    const float* dlr = dl + b * 512;
    const float* dwr = dw + i * 512;
    float acc = 0.f;
#pragma unroll 8
    for (int d = 0; d < 512; d++) acc = fmaf(dlr[d], dwr[d], acc);
    g_style[idx] = acc * DENSE_SCALE + db[i];
}

__global__ void k_wprep(const float* __restrict__ w) {
    int idx = blockIdx.x * 256 + threadIdx.x;   // o*512 + i
    const float* wp = w + (size_t)idx * 9;
    float s2 = 0.f;
#pragma unroll
    for (int t = 0; t < 9; t++) {
        float v = wp[t];
        s2 = fmaf(v, v, s2);
        g_wh[(size_t)t * (CO * CI) + idx] = __float2half_rn(v * CONV_SCALE);
    }
    g_w2[idx] = s2;
}

__global__ void k_demod() {
    int idx = blockIdx.x * 256 + threadIdx.x;
    int b = idx >> 9, o = idx & 511;
    const float* w2r = g_w2 + o * 512;
    const float* sr  = g_style + b * 512;
    float acc = 0.f;
#pragma unroll 8
    for (int i = 0; i < 512; i++) { float s = sr[i]; acc = fmaf(w2r[i], s * s, acc); }
    g_d[idx] = rsqrtf(acc * CONV_SCALE2 + 1e-8f);
}

// NCHW fp32 -> NHWC fp16 (modulated). grid (16 ci-tiles, 64 h, 8 b), 256 thr.
__global__ void k_xs_nhwc(const float* __restrict__ x) {
    __shared__ __half sm[64][40];
    int b = blockIdx.z, h = blockIdx.y, c0 = blockIdx.x * 32;
    int t = threadIdx.x;
#pragma unroll
    for (int it = 0; it < 8; it++) {
        int idx = it * 256 + t;
        int ci = idx >> 6, w = idx & 63;
        float v = x[(((size_t)b * 512 + c0 + ci) * 64 + h) * 64 + w];
        sm[w][ci] = __float2half_rn(v * g_style[b * 512 + c0 + ci]);
    }
    __syncthreads();
    int w = t >> 2, q = t & 3;
    uint4 val = *(const uint4*)&sm[w][q * 8];
    *(uint4*)&g_xs2[(((size_t)b * 64 + h) * 64 + w) * 512 + c0 + q * 8] = val;
}

// ---------------- conv: pipelined cp.async + mma.sync ----------------
__device__ __forceinline__ uint32_t s2u(const void* p) {
    return (uint32_t)__cvta_generic_to_shared(p);
}
__device__ __forceinline__ void ldsm4(uint32_t* r, uint32_t a) {
    asm volatile("ldmatrix.sync.aligned.m8n8.x4.shared.b16 {%0,%1,%2,%3}, [%4];"
                 : "=r"(r[0]), "=r"(r[1]), "=r"(r[2]), "=r"(r[3]) : "r"(a));
}
__device__ __forceinline__ void mma16816(float* c, const uint32_t* a, uint32_t b0, uint32_t b1) {
    asm volatile("mma.sync.aligned.m16n8k16.row.col.f32.f16.f16.f32 "
                 "{%0,%1,%2,%3}, {%4,%5,%6,%7}, {%8,%9}, {%0,%1,%2,%3};"
                 : "+f"(c[0]), "+f"(c[1]), "+f"(c[2]), "+f"(c[3])
                 : "r"(a[0]), "r"(a[1]), "r"(a[2]), "r"(a[3]), "r"(b0), "r"(b1));
}
__device__ __forceinline__ void cpa16(uint32_t d, const void* s, int ssz) {
    asm volatile("cp.async.cg.shared.global [%0], [%1], 16, %2;"
                 :: "r"(d), "l"(s), "r"(ssz) : "memory");
}
__device__ __forceinline__ void cp_commit() {
    asm volatile("cp.async.commit_group;" ::: "memory");
}
__device__ __forceinline__ void cp_wait3() {
    asm volatile("cp.async.wait_group 3;" ::: "memory");
}

// smem: A = 5 bufs x (128 o x 80B), B = 2 bufs x (396 px x 80B)
#define A_BUF_B   10240
#define B_BUF_B   31680
#define SM_B_OFF  (5 * A_BUF_B)
#define SM_TOTAL  (SM_B_OFF + 2 * B_BUF_B)
#define ITERS     144

__global__ __launch_bounds__(512, 1) void k_conv(float* __restrict__ out) {
    extern __shared__ char smraw[];
    char* As = smraw;
    char* Bs = smraw + SM_B_OFF;

    int tid = threadIdx.x, lane = tid & 31, warp = tid >> 5;
    int wm = warp & 3, wn = warp >> 2;
    int ob = blockIdx.x * 128;
    int h0 = blockIdx.y * 4;
    int b  = blockIdx.z;

    float acc[2][8][4];
#pragma unroll
    for (int i = 0; i < 2; i++)
#pragma unroll
        for (int j = 0; j < 8; j++)
#pragma unroll
            for (int k = 0; k < 4; k++) acc[i][j][k] = 0.f;

    // per-thread A-load coords: o row = tid>>2, 16B chunk q = tid&3
    int aro = tid >> 2, aq = tid & 3;
    // per-thread B-load coords (4 slots of 16B each)
    const __half* xb = g_xs2 + (size_t)b * (64 * 64 * 512);

    auto issueA = [&](int it) {
        int c = it / 9, tap = it - c * 9;
        uint32_t dst = s2u(As + (it % 5) * A_BUF_B + aro * 80 + aq * 16);
        const __half* src = g_wh + ((size_t)tap * (CO * CI) + (ob + aro) * 512 + c * 32 + aq * 8);
        cpa16(dst, src, 16);
    };
    auto issueB = [&](int c) {
        char* dbase = Bs + (c & 1) * B_BUF_B;
#pragma unroll
        for (int k = 0; k < 4; k++) {
            int idx = tid + 512 * k;
            if (idx < 1584) {
                int pixel = idx >> 2, q = idx & 3;
                int r = pixel / 66, cl = pixel - r * 66;
                int ri = h0 - 1 + r, wi = cl - 1;
                bool inb = ((unsigned)ri < 64u) && ((unsigned)wi < 64u);
                int rc = inb ? ri : 0, wc = inb ? wi : 0;
                uint32_t dst = s2u(dbase + pixel * 80 + q * 16);
                const __half* src = xb + (((size_t)rc * 64 + wc) * 512 + c * 32 + q * 8);
                cpa16(dst, src, inb ? 16 : 0);
            }
        }
    };

    // prologue: groups carrying A(0..3), B(0)
    issueB(0); issueA(0); cp_commit();
    issueA(1); cp_commit();
    issueA(2); cp_commit();
    issueA(3); cp_commit();

    uint32_t aLane = (uint32_t)((wm * 32 + (lane & 15)) * 80 + ((lane >> 4) << 4));
    uint32_t bLane = (uint32_t)(lane * 80);

    int c = 0, tap = 0;
    for (int it = 0; it < ITERS; ++it) {
        cp_wait3();            // A(it), B(c) complete (this thread's groups)
        __syncthreads();       // ...and everyone else's; also fences old reads

        {   // prefetch it+4
            int nit = it + 4;
            if (nit < ITERS) {
                issueA(nit);
                if (nit % 9 == 0) issueB(nit / 9);
            }
            cp_commit();
        }

        int dy = tap / 3, dx = tap - dy * 3;
        uint32_t aB = s2u(As + (it % 5) * A_BUF_B) + aLane;
        uint32_t bB = s2u(Bs + (c & 1) * B_BUF_B) + (uint32_t)(((wn + dy) * 66 + dx) * 80) + bLane;

#pragma unroll
        for (int k0 = 0; k0 < 2; k0++) {
            uint32_t a0[4], a1[4], p[4], q[4];
            ldsm4(a0, aB + k0 * 32);
            ldsm4(a1, aB + 16 * 80 + k0 * 32);
            // pixels 0-31
            ldsm4(p, bB + k0 * 32);
            ldsm4(q, bB + k0 * 32 + 16);
#pragma unroll
            for (int j = 0; j < 4; j++) {
                mma16816(acc[0][j], a0, p[j], q[j]);
                mma16816(acc[1][j], a1, p[j], q[j]);
            }
            // pixels 32-63
            ldsm4(p, bB + 32 * 80 + k0 * 32);
            ldsm4(q, bB + 32 * 80 + k0 * 32 + 16);
#pragma unroll
            for (int j = 0; j < 4; j++) {
                mma16816(acc[0][4 + j], a0, p[j], q[j]);
                mma16816(acc[1][4 + j], a1, p[j], q[j]);
            }
        }

        if (++tap == 9) { tap = 0; ++c; }
    }

    // ---- epilogue: demod scale + store ----
    int hrow = h0 + wn;
#pragma unroll
    for (int i = 0; i < 2; i++) {
        int o = ob + wm * 32 + i * 16 + (lane >> 2);
        float d1 = g_d[b * 512 + o];
        float d2 = g_d[b * 512 + o + 8];
        float* p0 = out + ((size_t)(b * 512 + o) * 4096) + hrow * 64 + ((lane & 3) << 1);
#pragma unroll
        for (int j = 0; j < 8; j++) {
            float2 v0, v1;
            v0.x = acc[i][j][0] * d1; v0.y = acc[i][j][1] * d1;
            v1.x = acc[i][j][2] * d2; v1.y = acc[i][j][3] * d2;
            *(float2*)(p0 + j * 8) = v0;
            *(float2*)(p0 + 8 * 4096 + j * 8) = v1;
        }
    }
}

// ---------------- launcher ----------------
extern "C" void kernel_launch(void* const* d_in, const int* in_sizes, int n_in,
                              void* d_out, int out_size) {
    const float* x  = (const float*)d_in[0];
    const float* dl = (const float*)d_in[1];
    const float* w  = (const float*)d_in[2];
    const float* dw = (const float*)d_in[3];
    const float* db = (const float*)d_in[4];
    float* out = (float*)d_out;

    k_style<<<16, 256>>>(dl, dw, db);
    k_wprep<<<1024, 256>>>(w);
    k_demod<<<16, 256>>>();
    k_xs_nhwc<<<dim3(16, 64, 8), 256>>>(x);

    cudaFuncSetAttribute(k_conv, cudaFuncAttributeMaxDynamicSharedMemorySize, SM_TOTAL);
    k_conv<<<dim3(4, 16, 8), 512, SM_TOTAL>>>(out);
}

// round 7
// speedup vs baseline: 2.1384x; 1.0113x over previous
#include <cuda_runtime.h>
#include <cuda_fp16.h>
#include <cstdint>

// Problem constants
#define NB 8
#define CI 512
#define CO 512
#define HH 64
#define WW 64
#define DENSE_SCALE 0.04419417382415922f
#define CONV_SCALE  0.014731391274719742f
#define CONV_SCALE2 (1.0f/4608.0f)

// ---------------- device scratch ----------------
__device__ float  g_style[NB*CI];
__device__ float  g_w2[CO*CI];
__device__ float  g_d[NB*CO];
__device__ __align__(1024) __half g_wh[(size_t)9*CO*CI];          // [tap][o][ci]
__device__ __align__(1024) __half g_xs2[(size_t)NB*HH*WW*CI];     // NHWC fp16

// ---------------- prep kernels ----------------
__global__ void k_style(const float* __restrict__ dl, const float* __restrict__ dw,
                        const float* __restrict__ db) {
    int idx = blockIdx.x * 256 + threadIdx.x;
    int b = idx >> 9, i = idx & 511;
    const float* dlr = dl + b * 512;
    const float* dwr = dw + i * 512;
    float acc = 0.f;
#pragma unroll 8
    for (int d = 0; d < 512; d++) acc = fmaf(dlr[d], dwr[d], acc);
    g_style[idx] = acc * DENSE_SCALE + db[i];
}

__global__ void k_wprep(const float* __restrict__ w) {
    int idx = blockIdx.x * 256 + threadIdx.x;   // o*512 + i
    const float* wp = w + (size_t)idx * 9;
    float s2 = 0.f;
#pragma unroll
    for (int t = 0; t < 9; t++) {
        float v = wp[t];
        s2 = fmaf(v, v, s2);
        g_wh[(size_t)t * (CO * CI) + idx] = __float2half_rn(v * CONV_SCALE);
    }
    g_w2[idx] = s2;
}

__global__ void k_demod() {
    int idx = blockIdx.x * 256 + threadIdx.x;
    int b = idx >> 9, o = idx & 511;
    const float* w2r = g_w2 + o * 512;
    const float* sr  = g_style + b * 512;
    float acc = 0.f;
#pragma unroll 8
    for (int i = 0; i < 512; i++) { float s = sr[i]; acc = fmaf(w2r[i], s * s, acc); }
    g_d[idx] = rsqrtf(acc * CONV_SCALE2 + 1e-8f);
}

// NCHW fp32 -> NHWC fp16 (modulated). grid (16 ci-tiles, 64 h, 8 b), 256 thr.
__global__ void k_xs_nhwc(const float* __restrict__ x) {
    __shared__ __half sm[64][40];
    int b = blockIdx.z, h = blockIdx.y, c0 = blockIdx.x * 32;
    int t = threadIdx.x;
#pragma unroll
    for (int it = 0; it < 8; it++) {
        int idx = it * 256 + t;
        int ci = idx >> 6, w = idx & 63;
        float v = x[(((size_t)b * 512 + c0 + ci) * 64 + h) * 64 + w];
        sm[w][ci] = __float2half_rn(v * g_style[b * 512 + c0 + ci]);
    }
    __syncthreads();
    int w = t >> 2, q = t & 3;
    uint4 val = *(const uint4*)&sm[w][q * 8];
    *(uint4*)&g_xs2[(((size_t)b * 64 + h) * 64 + w) * 512 + c0 + q * 8] = val;
}

// ---------------- conv: pipelined cp.async + mma.sync ----------------
__device__ __forceinline__ uint32_t s2u(const void* p) {
    return (uint32_t)__cvta_generic_to_shared(p);
}
__device__ __forceinline__ void ldsm4(uint32_t* r, uint32_t a) {
    asm volatile("ldmatrix.sync.aligned.m8n8.x4.shared.b16 {%0,%1,%2,%3}, [%4];"
                 : "=r"(r[0]), "=r"(r[1]), "=r"(r[2]), "=r"(r[3]) : "r"(a));
}
__device__ __forceinline__ void mma16816(float* c, const uint32_t* a, uint32_t b0, uint32_t b1) {
    asm volatile("mma.sync.aligned.m16n8k16.row.col.f32.f16.f16.f32 "
                 "{%0,%1,%2,%3}, {%4,%5,%6,%7}, {%8,%9}, {%0,%1,%2,%3};"
                 : "+f"(c[0]), "+f"(c[1]), "+f"(c[2]), "+f"(c[3])
                 : "r"(a[0]), "r"(a[1]), "r"(a[2]), "r"(a[3]), "r"(b0), "r"(b1));
}
__device__ __forceinline__ void cpa16(uint32_t d, const void* s, int ssz) {
    asm volatile("cp.async.cg.shared.global [%0], [%1], 16, %2;"
                 :: "r"(d), "l"(s), "r"(ssz) : "memory");
}
__device__ __forceinline__ void cp_commit() {
    asm volatile("cp.async.commit_group;" ::: "memory");
}
__device__ __forceinline__ void cp_wait3() {
    asm volatile("cp.async.wait_group 3;" ::: "memory");
}

// smem: A = 5 bufs x (128 o x 80B), B = 2 bufs x (396 px x 80B)
#define A_BUF_B   10240
#define B_BUF_B   31680
#define SM_B_OFF  (5 * A_BUF_B)
#define SM_TOTAL  (SM_B_OFF + 2 * B_BUF_B)
#define ITERS     144

// 256 thr / 8 warps. Warp = 32 o (wm) x 128 px (wn half of 256). 128 accum regs.
__global__ __launch_bounds__(256, 1) void k_conv(float* __restrict__ out) {
    extern __shared__ char smraw[];
    char* As = smraw;
    char* Bs = smraw + SM_B_OFF;

    int tid = threadIdx.x, lane = tid & 31, warp = tid >> 5;
    int wm = warp & 3, wn = warp >> 2;
    int ob = blockIdx.x * 128;
    int h0 = blockIdx.y * 4;
    int b  = blockIdx.z;

    float acc[2][4][4][4];   // [a-half 16o][g: 32px group][j: 8px][4]
#pragma unroll
    for (int i = 0; i < 2; i++)
#pragma unroll
        for (int g = 0; g < 4; g++)
#pragma unroll
            for (int j = 0; j < 4; j++)
#pragma unroll
                for (int k = 0; k < 4; k++) acc[i][g][j][k] = 0.f;

    const __half* xb = g_xs2 + (size_t)b * (64 * 64 * 512);

    auto issueA = [&](int it) {   // 128 rows x 4 chunks = 512; 2 per thread
        int c = it / 9, tap = it - c * 9;
        char* abase = As + (it % 5) * A_BUF_B;
        const __half* wsrc = g_wh + ((size_t)tap * (CO * CI) + (size_t)ob * 512 + c * 32);
#pragma unroll
        for (int k = 0; k < 2; k++) {
            int idx = tid + 256 * k;
            int row = idx >> 2, q = idx & 3;
            cpa16(s2u(abase + row * 80 + q * 16), wsrc + (size_t)row * 512 + q * 8, 16);
        }
    };
    auto issueB = [&](int c) {    // 396 px x 4 chunks = 1584; up to 7 per thread
        char* dbase = Bs + (c & 1) * B_BUF_B;
#pragma unroll
        for (int k = 0; k < 7; k++) {
            int idx = tid + 256 * k;
            if (idx < 1584) {
                int pixel = idx >> 2, q = idx & 3;
                int r = pixel / 66, cl = pixel - r * 66;
                int ri = h0 - 1 + r, wi = cl - 1;
                bool inb = ((unsigned)ri < 64u) && ((unsigned)wi < 64u);
                int rc = inb ? ri : 0, wc = inb ? wi : 0;
                cpa16(s2u(dbase + pixel * 80 + q * 16),
                      xb + (((size_t)rc * 64 + wc) * 512 + c * 32 + q * 8), inb ? 16 : 0);
            }
        }
    };

    // prologue: groups carrying A(0..3), B(0)
    issueB(0); issueA(0); cp_commit();
    issueA(1); cp_commit();
    issueA(2); cp_commit();
    issueA(3); cp_commit();

    uint32_t aLane = (uint32_t)((wm * 32 + (lane & 15)) * 80 + ((lane >> 4) << 4));

    int c = 0, tap = 0;
    for (int it = 0; it < ITERS; ++it) {
        cp_wait3();
        __syncthreads();

        {   // prefetch it+4
            int nit = it + 4;
            if (nit < ITERS) {
                issueA(nit);
                if (nit % 9 == 0) issueB(nit / 9);
            }
            cp_commit();
        }

        int dy = tap / 3, dx = tap - dy * 3;
        uint32_t aB = s2u(As + (it % 5) * A_BUF_B) + aLane;
        uint32_t bRow = s2u(Bs + (c & 1) * B_BUF_B);

#pragma unroll
        for (int k0 = 0; k0 < 2; k0++) {
            uint32_t a0[4], a1[4];
            ldsm4(a0, aB + k0 * 32);              // o rows wm*32 + 0..15
            ldsm4(a1, aB + 16 * 80 + k0 * 32);    // o rows wm*32 + 16..31
#pragma unroll
            for (int g = 0; g < 4; g++) {
                int rl = wn * 2 + (g >> 1) + dy;
                int cl = ((g & 1) << 5) + dx + lane;
                uint32_t ba = bRow + (uint32_t)((rl * 66 + cl) * 80) + k0 * 32;
                uint32_t p[4], q[4];
                ldsm4(p, ba);
                ldsm4(q, ba + 16);
#pragma unroll
                for (int j = 0; j < 4; j++) {
                    mma16816(acc[0][g][j], a0, p[j], q[j]);
                    mma16816(acc[1][g][j], a1, p[j], q[j]);
                }
            }
        }

        if (++tap == 9) { tap = 0; ++c; }
    }

    // ---- epilogue: demod scale + store ----
#pragma unroll
    for (int i = 0; i < 2; i++) {
        int o = ob + wm * 32 + i * 16 + (lane >> 2);
        float d1 = g_d[b * 512 + o];
        float d2 = g_d[b * 512 + o + 8];
        float* p0 = out + ((size_t)(b * 512 + o) * 4096) + ((lane & 3) << 1);
#pragma unroll
        for (int g = 0; g < 4; g++) {
#pragma unroll
            for (int j = 0; j < 4; j++) {
                int nsub = wn * 128 + g * 32 + j * 8;
                int h = h0 + (nsub >> 6);
                int col = nsub & 63;
                float2 v0, v1;
                v0.x = acc[i][g][j][0] * d1; v0.y = acc[i][g][j][1] * d1;
                v1.x = acc[i][g][j][2] * d2; v1.y = acc[i][g][j][3] * d2;
                *(float2*)(p0 + h * 64 + col) = v0;
                *(float2*)(p0 + 8 * 4096 + h * 64 + col) = v1;
            }
        }
    }
}

// ---------------- launcher ----------------
extern "C" void kernel_launch(void* const* d_in, const int* in_sizes, int n_in,
                              void* d_out, int out_size) {
    const float* x  = (const float*)d_in[0];
    const float* dl = (const float*)d_in[1];
    const float* w  = (const float*)d_in[2];
    const float* dw = (const float*)d_in[3];
    const float* db = (const float*)d_in[4];
    float* out = (float*)d_out;

    k_style<<<16, 256>>>(dl, dw, db);
    k_wprep<<<1024, 256>>>(w);
    k_demod<<<16, 256>>>();
    k_xs_nhwc<<<dim3(16, 64, 8), 256>>>(x);

    cudaFuncSetAttribute(k_conv, cudaFuncAttributeMaxDynamicSharedMemorySize, SM_TOTAL);
    k_conv<<<dim3(4, 16, 8), 256, SM_TOTAL>>>(out);
}